// round 17
// baseline (speedup 1.0000x reference)
#include <cuda_runtime.h>
#include <cuda_fp16.h>
#include <cstdint>

#define Bv 128
#define Nv 512
#define Xv 128
#define Hv 256
#define BN (Bv*Nv)           // 65536
#define GSZ (BN*Hv)          // 16777216 floats per gate buffer

// 6 precomputed gate-input buffers: 0=fg_x 1=ig_x 2=in_x 3=og_x 4=tm1 5=tm2
__device__ float g_pre[6][GSZ];

// Pre-converted W_x matrices (hi/lo fp16 planes), order matches gate index:
// 0=fg 1=ig 2=in 3=og 4=tg1 5=tg2
__device__ __half g_wxh[6][Hv * Xv];   // 6 x 32768
__device__ __half g_wxl[6][Hv * Xv];

__device__ __forceinline__ float sigmoidf_(float v) { return 1.0f / (1.0f + __expf(-v)); }

// exp-based tanh: ~5 instr, rel err ~1e-6. Args bounded, no overflow path.
__device__ __forceinline__ float tanh_fast_(float x) {
    float e = __expf(-2.0f * x);
    return __fdividef(1.0f - e, 1.0f + e);
}

__device__ __forceinline__ uint32_t smem_u32_(const void* p) {
    uint32_t a;
    asm("{ .reg .u64 t; cvta.to.shared.u64 t, %1; cvt.u32.u64 %0, t; }" : "=r"(a) : "l"(p));
    return a;
}

// ---- tensor-core helpers ----
__device__ __forceinline__ void ldsm4t_(uint32_t* d, uint32_t addr) {
    asm volatile("ldmatrix.sync.aligned.m8n8.x4.trans.shared.b16 {%0,%1,%2,%3}, [%4];"
        : "=r"(d[0]), "=r"(d[1]), "=r"(d[2]), "=r"(d[3]) : "r"(addr));
}
__device__ __forceinline__ void mma16816_(float* c, const uint32_t* a, const uint32_t* b) {
    asm volatile(
        "mma.sync.aligned.m16n8k16.row.col.f32.f16.f16.f32 "
        "{%0,%1,%2,%3}, {%4,%5,%6,%7}, {%8,%9}, {%0,%1,%2,%3};"
        : "+f"(c[0]), "+f"(c[1]), "+f"(c[2]), "+f"(c[3])
        : "r"(a[0]), "r"(a[1]), "r"(a[2]), "r"(a[3]), "r"(b[0]), "r"(b[1]));
}
// Split fp32 pair into hi-fp16x2 and lo-residual-fp16x2.
__device__ __forceinline__ void split2_(float2 v, uint32_t& hi, uint32_t& lo) {
    __half h0 = __float2half_rn(v.x), h1 = __float2half_rn(v.y);
    float r0 = v.x - __half2float(h0), r1 = v.y - __half2float(h1);
    __half2 H = __halves2half2(h0, h1);
    __half2 L = __floats2half2_rn(r0, r1);
    hi = *(uint32_t*)&H;
    lo = *(uint32_t*)&L;
}

// Bulk DSMEM copy: local smem src -> rank rk's smem dst (same-offset address
// space), crediting rank rk's mbarrier with complete_tx bytes.
__device__ __forceinline__ void bulk_copy_rank_(uint32_t dst, uint32_t src,
                                                uint32_t mb, uint32_t rank,
                                                uint32_t bytes) {
    asm volatile(
        "{\n\t"
        ".reg .b32 rd, rm;\n\t"
        "mapa.shared::cluster.u32 rd, %0, %3;\n\t"
        "mapa.shared::cluster.u32 rm, %2, %3;\n\t"
        "cp.async.bulk.shared::cluster.shared::cta.mbarrier::complete_tx::bytes [rd], [%1], %4, [rm];\n\t"
        "}"
        :: "r"(dst), "r"(src), "r"(mb), "r"(rank), "r"(bytes) : "memory");
}

#define MBAR_INIT_(a, c) \
    asm volatile("mbarrier.init.shared.b64 [%0], %1;" :: "r"(a), "r"(c) : "memory")

#define MBAR_ARRIVE_EXPECT_(a, bytes) \
    asm volatile("mbarrier.arrive.expect_tx.shared.b64 _, [%0], %1;" \
                 :: "r"(a), "r"(bytes) : "memory")

#define FENCE_ASYNC_() asm volatile("fence.proxy.async.shared::cta;" ::: "memory")

__device__ __forceinline__ void mbar_wait_(uint32_t a, uint32_t parity) {
    asm volatile(
        "{\n\t"
        ".reg .pred P;\n\t"
        "WL_%=:\n\t"
        "mbarrier.try_wait.parity.acquire.cta.shared::cta.b64 P, [%0], %1, 0x989680;\n\t"
        "@P bra.uni WD_%=;\n\t"
        "bra.uni WL_%=;\n\t"
        "WD_%=:\n\t"
        "}"
        :: "r"(a), "r"(parity) : "memory");
}

#define CLUSTER_SYNC_() do { \
    asm volatile("barrier.cluster.arrive.aligned;" ::: "memory"); \
    asm volatile("barrier.cluster.wait.aligned;"   ::: "memory"); \
} while (0)

#define BAR_SYNC_(id, cnt) \
    asm volatile("bar.sync %0, %1;" :: "r"(id), "r"(cnt) : "memory")

// ============================================================================
// Phase 0: one-shot conversion of the 6 W_x matrices to hi/lo fp16 planes.
// 196608 elements, grid 768 x 256.
// ============================================================================
__global__ void convert_wx_kernel(
    const float* __restrict__ fg, const float* __restrict__ ig,
    const float* __restrict__ inw, const float* __restrict__ og,
    const float* __restrict__ t1, const float* __restrict__ t2)
{
    const int i = blockIdx.x * 256 + threadIdx.x;
    const int m = i >> 15;
    const int e = i & 32767;
    const float* src = (m == 0) ? fg : (m == 1) ? ig : (m == 2) ? inw
                     : (m == 3) ? og : (m == 4) ? t1 : t2;
    const float v = src[e];
    const __half hh = __float2half_rn(v);
    g_wxh[m][e] = hh;
    g_wxl[m][e] = __float2half_rn(v - __half2float(hh));
}

// ============================================================================
// Phase 1: precompute, FUSED: one block per bn-tile converts x ONCE and loops
// over all 24 (gate, h-subtile) GEMMs, loading PRE-CONVERTED fp16 weight
// fragments (no per-block split math). grid 512, block 256, 2 CTAs/SM.
// ============================================================================

#define XP_STRIDE 136
#define PLANE_HALVES (128 * XP_STRIDE)          // 17408 halves
#define PC_SMEM_BYTES (2 * PLANE_HALVES * 2)    // 69632 B

__global__ void __launch_bounds__(256, 2) precompute_kernel(
    const float* __restrict__ x, const float* __restrict__ tvec,
    const float* __restrict__ fg_b, const float* __restrict__ ig_b,
    const float* __restrict__ in_b,
    const float* __restrict__ og_b, const float* __restrict__ og_w_t,
    const float* __restrict__ tg1_b, const float* __restrict__ tg1_w_t,
    const float* __restrict__ tg2_b, const float* __restrict__ tg2_w_t)
{
    extern __shared__ __half xp[];   // [plane 2][k 128][m 136]

    const int tid  = threadIdx.x;
    const int lane = tid & 31;
    const int w    = tid >> 5;       // 0..7
    const int bn0  = blockIdx.x * 128;

    // Convert x tile [128 m][128 k] fp32 -> k-major hi/lo planes (ONCE).
    for (int i = tid; i < 4096; i += 256) {
        const int m  = i >> 5;
        const int kq = i & 31;
        float4 v = *(const float4*)(x + (size_t)(bn0 + m) * 128 + kq * 4);
        const float vv[4] = { v.x, v.y, v.z, v.w };
        #pragma unroll
        for (int s = 0; s < 4; s++) {
            const int k = kq * 4 + s;
            __half hh = __float2half_rn(vv[s]);
            xp[k * XP_STRIDE + m]                = hh;
            xp[PLANE_HALVES + k * XP_STRIDE + m] = __float2half_rn(vv[s] - __half2float(hh));
        }
    }
    __syncthreads();

    const uint32_t sbase = smem_u32_(xp);
    const int wm = w & 1;    // m half (64 rows)
    const int wn = w >> 1;   // n quarter (16 cols)
    const int krow_off = (lane & 7) + ((lane >> 4) << 3);
    const int bcol     = ((lane >> 3) & 1) << 3;
    const int mwbase   = wm * 64 + bcol;

    #pragma unroll 1
    for (int ht = 0; ht < 24; ++ht) {
        const int gate = ht >> 2;
        const int hl0  = (ht & 3) * 64;

        const float* bptr; const float* tptr = nullptr;
        switch (gate) {
            case 0:  bptr = fg_b;  break;
            case 1:  bptr = ig_b;  break;
            case 2:  bptr = in_b;  break;
            case 3:  bptr = og_b;  tptr = og_w_t;  break;
            case 4:  bptr = tg1_b; tptr = tg1_w_t; break;
            default: bptr = tg2_b; tptr = tg2_w_t; break;
        }
        const __half* Whi = g_wxh[gate];
        const __half* Wlo = g_wxl[gate];

        // W B-fragments: [nt 2][kt 8][pair 2], direct u32 loads (L2 hits).
        uint32_t bh[2][8][2], bl[2][8][2];
        #pragma unroll
        for (int nt = 0; nt < 2; nt++) {
            const int n = hl0 + wn * 16 + nt * 8 + (lane >> 2);
            const __half* Hh = Whi + (size_t)n * 128;
            const __half* Hl = Wlo + (size_t)n * 128;
            #pragma unroll
            for (int kt = 0; kt < 8; kt++) {
                const int kb = kt * 16 + (lane & 3) * 2;
                bh[nt][kt][0] = *(const uint32_t*)(Hh + kb);
                bh[nt][kt][1] = *(const uint32_t*)(Hh + kb + 8);
                bl[nt][kt][0] = *(const uint32_t*)(Hl + kb);
                bl[nt][kt][1] = *(const uint32_t*)(Hl + kb + 8);
            }
        }

        float2 bias2[2], tw2[2];
        #pragma unroll
        for (int nt = 0; nt < 2; nt++) {
            const int cg = hl0 + wn * 16 + nt * 8 + (lane & 3) * 2;
            bias2[nt] = *(const float2*)(bptr + cg);
            tw2[nt]   = (tptr != nullptr) ? *(const float2*)(tptr + cg) : make_float2(0.f, 0.f);
        }
        float* outg = &g_pre[gate][0];

        #pragma unroll 1
        for (int half = 0; half < 2; half++) {
            float acc[2][2][4];
            #pragma unroll
            for (int mt = 0; mt < 2; mt++)
                #pragma unroll
                for (int nt = 0; nt < 2; nt++) {
                    acc[mt][nt][0] = 0.f; acc[mt][nt][1] = 0.f;
                    acc[mt][nt][2] = 0.f; acc[mt][nt][3] = 0.f;
                }

            #pragma unroll
            for (int kt = 0; kt < 8; kt++) {
                #pragma unroll
                for (int mt = 0; mt < 2; mt++) {
                    const int mtg = half * 2 + mt;
                    const uint32_t addr = sbase
                        + 2u * (uint32_t)((kt * 16 + krow_off) * XP_STRIDE + mwbase + mtg * 16);
                    uint32_t ah[4], al[4];
                    ldsm4t_(ah, addr);
                    ldsm4t_(al, addr + 2u * PLANE_HALVES);
                    #pragma unroll
                    for (int nt = 0; nt < 2; nt++) {
                        mma16816_(acc[mt][nt], ah, bh[nt][kt]);
                        mma16816_(acc[mt][nt], al, bh[nt][kt]);
                        mma16816_(acc[mt][nt], ah, bl[nt][kt]);
                    }
                }
            }

            // Epilogue: bias / t terms / activations; float2 stores to g_pre.
            #pragma unroll
            for (int mt = 0; mt < 2; mt++) {
                const int mtg = half * 2 + mt;
                const int r0 = bn0 + wm * 64 + mtg * 16 + (lane >> 2);
                const int r1 = r0 + 8;
                float tv0 = 0.f, tv1 = 0.f;
                if (gate >= 3) { tv0 = tvec[r0]; tv1 = tvec[r1]; }
                #pragma unroll
                for (int nt = 0; nt < 2; nt++) {
                    const int cg = hl0 + wn * 16 + nt * 8 + (lane & 3) * 2;
                    const float* a = acc[mt][nt];
                    float2 o0, o1;
                    if (gate < 3) {
                        o0 = make_float2(a[0] + bias2[nt].x, a[1] + bias2[nt].y);
                        o1 = make_float2(a[2] + bias2[nt].x, a[3] + bias2[nt].y);
                    } else if (gate == 3) {
                        o0 = make_float2(a[0] + tw2[nt].x * tv0 + bias2[nt].x,
                                         a[1] + tw2[nt].y * tv0 + bias2[nt].y);
                        o1 = make_float2(a[2] + tw2[nt].x * tv1 + bias2[nt].x,
                                         a[3] + tw2[nt].y * tv1 + bias2[nt].y);
                    } else {
                        o0 = make_float2(sigmoidf_(a[0] + tanh_fast_(tw2[nt].x * tv0) + bias2[nt].x),
                                         sigmoidf_(a[1] + tanh_fast_(tw2[nt].y * tv0) + bias2[nt].y));
                        o1 = make_float2(sigmoidf_(a[2] + tanh_fast_(tw2[nt].x * tv1) + bias2[nt].x),
                                         sigmoidf_(a[3] + tanh_fast_(tw2[nt].y * tv1) + bias2[nt].y));
                    }
                    *(float2*)(outg + (size_t)r0 * 256 + cg) = o0;
                    *(float2*)(outg + (size_t)r1 * 256 + cg) = o1;
                }
            }
        }
    }
}

// ============================================================================
// Phase 2: recurrence — R13 structure with plane-interleaved hbuf (R10 proven
// layout): hbuf [par][k 256][pl 2][b 16], one 2 KB copy per rank (8 copies,
// 8 mbar credits per step instead of 16).
// ============================================================================

#define REC_THREADS 512
#define HBUF_B   0        // half [par 2][k 256][pl 2][b 16] = 32768 B
#define STG_B    32768    // half [par 2][j 32][pl 2][b 16] = 4096 B
#define CRED_B   36864    // float [kg 4][b 8][136] = 17408 B
#define MBAR_B   54272    // 2 x u64
#define SMEM_REC_BYTES 54400

__global__ void __cluster_dims__(8, 1, 1) __launch_bounds__(REC_THREADS, 1) lstm_rec_kernel(
    const float* __restrict__ fg_w_c, const float* __restrict__ fg_w_h,
    const float* __restrict__ ig_w_c, const float* __restrict__ ig_w_h,
    const float* __restrict__ in_w_h,
    const float* __restrict__ og_w_cn, const float* __restrict__ og_w_h,
    float* __restrict__ out)
{
    extern __shared__ char smc[];
    __half* Sg   = (__half*)(smc + STG_B);
    float*  Cred = (float*)(smc + CRED_B);

    const int tid  = threadIdx.x;
    const int lane = tid & 31;
    const int w    = tid >> 5;         // 0..15
    const int r    = blockIdx.x & 7;
    const int grp  = blockIdx.x >> 3;
    const int ns   = w & 3;            // n-slice (32 cols)
    const int kg   = w >> 2;           // k-group (64 k)

    const uint32_t sbase = smem_u32_(smc);
    const uint32_t mb0 = sbase + MBAR_B;
    const uint32_t mb1 = mb0 + 8;

    uint32_t bh[4][4][2], bl[4][4][2];   // [nt][kt][pair]
    {
        const float* Wg0[4] = { ig_w_h, fg_w_h, in_w_h, og_w_h };
        #pragma unroll
        for (int nt = 0; nt < 4; nt++) {
            const int n  = ns * 32 + nt * 8 + (lane >> 2);
            const float* Wr = Wg0[n >> 5] + (size_t)(r * 32 + (n & 31)) * 256;
            #pragma unroll
            for (int kt = 0; kt < 4; kt++) {
                const int kb = kg * 64 + kt * 16 + (lane & 3) * 2;
                float2 v0 = *(const float2*)(Wr + kb);
                float2 v1 = *(const float2*)(Wr + kb + 8);
                split2_(v0, bh[nt][kt][0], bl[nt][kt][0]);
                split2_(v1, bh[nt][kt][1], bl[nt][kt][1]);
            }
        }
    }

    for (int i = tid; i < 9216; i += REC_THREADS) ((uint32_t*)smc)[i] = 0u;

    if (tid == 0) {
        MBAR_INIT_(mb0, 1);
        MBAR_INIT_(mb1, 1);
        MBAR_ARRIVE_EXPECT_(mb0, 16384);
        MBAR_ARRIVE_EXPECT_(mb1, 16384);
    }

    const int b_own = w;
    const int j_own = lane;
    const int jg    = r * 32 + j_own;
    const int bg    = grp * 8 + b_own;
    const float wc_ig = ig_w_c[jg];
    const float wc_fg = fg_w_c[jg];
    const float wc_og = og_w_cn[jg];
    const size_t rowoff = (size_t)bg * Nv * 256 + jg;

    __syncthreads();
    CLUSTER_SYNC_();

    float cmv = 0.0f, hnv = 0.0f;
    uint32_t ph0 = 0, ph1 = 0;

    float p0 = 0.f, p1 = 0.f, p2 = 0.f, p3 = 0.f, p4 = 0.f, p5 = 0.f;
    if (tid < 256) {
        p0 = __ldcs(&g_pre[0][rowoff]);
        p1 = __ldcs(&g_pre[1][rowoff]);
        p2 = __ldcs(&g_pre[2][rowoff]);
        p3 = __ldcs(&g_pre[3][rowoff]);
        p4 = __ldcs(&g_pre[4][rowoff]);
        p5 = __ldcs(&g_pre[5][rowoff]);
    }

    const int krow_off = (lane & 7) + ((lane >> 4) << 3);
    const int bcol16   = ((lane >> 3) & 1) << 4;

    #pragma unroll 1
    for (int n = 0; n < Nv; ++n) {
        const int q = n & 1;

        if (n != 0) {
            const uint32_t mb = q ? mb1 : mb0;
            mbar_wait_(mb, q ? ph1 : ph0);
            if (q) ph1 ^= 1; else ph0 ^= 1;
            if (tid == 0) MBAR_ARRIVE_EXPECT_(mb, 16384);
        }

        float q0 = 0.f, q1 = 0.f, q2 = 0.f, q3 = 0.f, q4 = 0.f, q5 = 0.f;
        if (tid < 256 && n + 1 < Nv) {
            const size_t off = rowoff + (size_t)(n + 1) * 256;
            q0 = __ldcs(&g_pre[0][off]); q1 = __ldcs(&g_pre[1][off]);
            q2 = __ldcs(&g_pre[2][off]); q3 = __ldcs(&g_pre[3][off]);
            q4 = __ldcs(&g_pre[4][off]); q5 = __ldcs(&g_pre[5][off]);
        }

        float c[4][4];
        #pragma unroll
        for (int nt = 0; nt < 4; nt++) { c[nt][0] = 0.f; c[nt][1] = 0.f; c[nt][2] = 0.f; c[nt][3] = 0.f; }

        #pragma unroll
        for (int kt = 0; kt < 4; kt++) {
            const uint32_t rowa = sbase + HBUF_B
                + (uint32_t)(q * 16384 + (kg * 64 + kt * 16 + krow_off) * 64 + bcol16);
            uint32_t ah[4], al[4];
            ldsm4t_(ah, rowa);        // hi plane (row bytes 0..31)
            ldsm4t_(al, rowa + 32);   // lo plane (row bytes 32..63)
            #pragma unroll
            for (int nt = 0; nt < 4; nt++) {
                mma16816_(c[nt], ah, bh[nt][kt]);
                mma16816_(c[nt], al, bh[nt][kt]);
                mma16816_(c[nt], ah, bl[nt][kt]);
            }
        }

        {
            const int bq = lane >> 2;
            #pragma unroll
            for (int nt = 0; nt < 4; nt++) {
                const int n0 = ns * 32 + nt * 8 + (lane & 3) * 2;
                *(float2*)&Cred[(kg * 8 + bq) * 136 + n0] = make_float2(c[nt][0], c[nt][1]);
            }
        }
        __syncthreads();

        if (tid < 256) {
            float s_ig = 0.f, s_fg = 0.f, s_in = 0.f, s_og = 0.f;
            #pragma unroll
            for (int kc = 0; kc < 4; kc++) {
                const float* rr = Cred + (kc * 8 + b_own) * 136 + j_own;
                s_ig += rr[0];
                s_fg += rr[32];
                s_in += rr[64];
                s_og += rr[96];
            }

            float ig  = sigmoidf_(wc_ig * cmv + s_ig + p1);
            float fg  = sigmoidf_(wc_fg * cmv + s_fg + p0);
            float inn = tanh_fast_(s_in + p2);
            float fc  = fg * cmv;
            float gi  = ig * inn;
            float cmh = fc + gi * p4;
            cmv       = fc + gi * p5;
            float og  = sigmoidf_(wc_og * cmh + s_og + p3);
            hnv       = og * tanh_fast_(cmh);

            if (n < Nv - 1) {
                const int qn = q ^ 1;
                // stage [par][j 32][pl 2][b 16]
                __half* S = Sg + qn * 1024 + j_own * 32 + b_own;
                __half hh = __float2half_rn(hnv);
                S[0]  = hh;
                S[16] = __float2half_rn(hnv - __half2float(hh));
                BAR_SYNC_(1, 256);
                if (tid < 8) {
                    FENCE_ASYNC_();
                    bulk_copy_rank_(
                        sbase + HBUF_B + (uint32_t)(qn * 16384 + (r * 32) * 64),
                        sbase + STG_B  + (uint32_t)(qn * 2048),
                        qn ? mb1 : mb0, (uint32_t)tid, 2048);
                }
            }
            p0 = q0; p1 = q1; p2 = q2; p3 = q3; p4 = q4; p5 = q5;
        }
    }

    CLUSTER_SYNC_();

    if (tid < 256) {
        out[(size_t)bg * 256 + jg]         = hnv;
        out[32768 + (size_t)bg * 256 + jg] = cmv;
    }
}

// ============================================================================
// Launch
// ============================================================================
extern "C" void kernel_launch(void* const* d_in, const int* in_sizes, int n_in,
                              void* d_out, int out_size)
{
    const float* x       = (const float*)d_in[0];
    const float* t       = (const float*)d_in[1];
    const float* fg_w_c  = (const float*)d_in[2];
    const float* fg_w_h  = (const float*)d_in[3];
    const float* fg_w_x  = (const float*)d_in[4];
    const float* fg_b    = (const float*)d_in[5];
    const float* ig_w_c  = (const float*)d_in[6];
    const float* ig_w_h  = (const float*)d_in[7];
    const float* ig_w_x  = (const float*)d_in[8];
    const float* ig_b    = (const float*)d_in[9];
    const float* in_w_h  = (const float*)d_in[10];
    const float* in_w_x  = (const float*)d_in[11];
    const float* in_b    = (const float*)d_in[12];
    const float* og_w_cn = (const float*)d_in[13];
    const float* og_w_h  = (const float*)d_in[14];
    const float* og_w_x  = (const float*)d_in[15];
    const float* og_b    = (const float*)d_in[16];
    const float* og_w_t  = (const float*)d_in[17];
    const float* tg1_w_x = (const float*)d_in[18];
    const float* tg1_w_t = (const float*)d_in[19];
    const float* tg1_b   = (const float*)d_in[20];
    const float* tg2_w_x = (const float*)d_in[21];
    const float* tg2_w_t = (const float*)d_in[22];
    const float* tg2_b   = (const float*)d_in[23];
    float* out = (float*)d_out;

    cudaFuncSetAttribute(precompute_kernel, cudaFuncAttributeMaxDynamicSharedMemorySize, PC_SMEM_BYTES);
    cudaFuncSetAttribute(lstm_rec_kernel,   cudaFuncAttributeMaxDynamicSharedMemorySize, SMEM_REC_BYTES);

    convert_wx_kernel<<<768, 256>>>(fg_w_x, ig_w_x, in_w_x, og_w_x, tg1_w_x, tg2_w_x);

    precompute_kernel<<<512, 256, PC_SMEM_BYTES>>>(
        x, t,
        fg_b, ig_b, in_b,
        og_b, og_w_t,
        tg1_b, tg1_w_t,
        tg2_b, tg2_w_t);

    lstm_rec_kernel<<<128, REC_THREADS, SMEM_REC_BYTES>>>(
        fg_w_c, fg_w_h, ig_w_c, ig_w_h, in_w_h, og_w_cn, og_w_h, out);
}